// round 9
// baseline (speedup 1.0000x reference)
#include <cuda_runtime.h>
#include <cuda_bf16.h>
#include <cstdint>

// Problem dims (fixed per reference setup_inputs)
#define M_DIM 65536
#define N_DIM 1024
#define K_DIM 768

// GEMM tiling: CTA 128x256, warp 64x64 (2x4 warps), BK=64, 4-stage cp.async
#define BM 128
#define BN 256
#define BK 64
#define NK (K_DIM / BK)            // 12
#define STAGES 4
#define A_BYTES (BM * 128)         // 128 rows x 128B (64 bf16)
#define B_BYTES (BN * 128)         // 256 rows x 128B
#define STAGE_BYTES (A_BYTES + B_BYTES)            // 49152
#define SMEM_DYN (1024 + STAGES * STAGE_BYTES)     // ~197.6 KB

// Scratch: normalized bf16 operands (device globals -- no allocation allowed)
__device__ __nv_bfloat16 g_embn[(size_t)M_DIM * K_DIM];
__device__ __nv_bfloat16 g_wn[(size_t)N_DIM * K_DIM];

// ---------------------------------------------------------------------------
// Row L2-normalize fp32 -> bf16. One warp per row (K=768: 6 float4 per lane).
// ---------------------------------------------------------------------------
__global__ void normalize_kernel(const float* __restrict__ in, int rows, int which) {
    int warp = (blockIdx.x * blockDim.x + threadIdx.x) >> 5;
    int lane = threadIdx.x & 31;
    if (warp >= rows) return;

    __nv_bfloat16* outbase = which ? g_wn : g_embn;

    const float4* src = (const float4*)(in + (size_t)warp * K_DIM);
    float4 v[6];
    float ss = 0.f;
#pragma unroll
    for (int i = 0; i < 6; i++) {
        v[i] = src[lane + i * 32];
        ss += v[i].x * v[i].x + v[i].y * v[i].y + v[i].z * v[i].z + v[i].w * v[i].w;
    }
#pragma unroll
    for (int o = 16; o > 0; o >>= 1) ss += __shfl_xor_sync(0xffffffffu, ss, o);

    float norm = fmaxf(sqrtf(ss), 1e-8f);   // torch cosine_similarity clamp
    float s = 1.0f / norm;

    __nv_bfloat162* dst = (__nv_bfloat162*)(outbase + (size_t)warp * K_DIM);
#pragma unroll
    for (int i = 0; i < 6; i++) {
        int idx = lane + i * 32;
        dst[idx * 2 + 0] = __floats2bfloat162_rn(v[i].x * s, v[i].y * s);
        dst[idx * 2 + 1] = __floats2bfloat162_rn(v[i].z * s, v[i].w * s);
    }
}

// ---------------------------------------------------------------------------
// helpers
// ---------------------------------------------------------------------------
__device__ __forceinline__ void cp16(uint32_t saddr, const void* g) {
    asm volatile("cp.async.cg.shared.global [%0], [%1], 16;" :: "r"(saddr), "l"(g));
}

__device__ __forceinline__ void mma16816(float* c, const uint32_t* a, const uint32_t* b) {
    asm volatile(
        "mma.sync.aligned.m16n8k16.row.col.f32.bf16.bf16.f32 "
        "{%0,%1,%2,%3}, {%4,%5,%6,%7}, {%8,%9}, {%0,%1,%2,%3};\n"
        : "+f"(c[0]), "+f"(c[1]), "+f"(c[2]), "+f"(c[3])
        : "r"(a[0]), "r"(a[1]), "r"(a[2]), "r"(a[3]), "r"(b[0]), "r"(b[1]));
}

#define LDSM_X4(r0, r1, r2, r3, addr) \
    asm volatile("ldmatrix.sync.aligned.m8n8.x4.shared.b16 {%0,%1,%2,%3}, [%4];" \
                 : "=r"(r0), "=r"(r1), "=r"(r2), "=r"(r3) : "r"(addr))

// ---------------------------------------------------------------------------
// bf16 mma.sync GEMM: C[M,N] = embn @ wn^T, epilogue 10*cos + (10 + 2e-7)
// smem rows are 128B (64 bf16), SW128-swizzled at 16B granularity:
//   addr(row, bytecol) = row*128 + (bytecol ^ ((row&7)<<4))
// ---------------------------------------------------------------------------
__global__ __launch_bounds__(256, 1) void gemm_kernel(float* __restrict__ C) {
    extern __shared__ char dsm[];
    const uint32_t raw  = (uint32_t)__cvta_generic_to_shared(dsm);
    const uint32_t data = (raw + 1023) & ~1023u;

    const int tid    = threadIdx.x;
    const int wid    = tid >> 5;
    const int lane   = tid & 31;
    const int warp_m = wid & 1;    // 2 warps along M -> 64 rows each
    const int warp_n = wid >> 1;   // 4 warps along N -> 64 cols each
    const int g  = lane >> 2;      // group 0..7
    const int t4 = lane & 3;

    const int m0 = blockIdx.y * BM;
    const int n0 = blockIdx.x * BN;

    float acc[4][8][4];
#pragma unroll
    for (int mi = 0; mi < 4; mi++)
#pragma unroll
        for (int ni = 0; ni < 8; ni++)
#pragma unroll
            for (int q = 0; q < 4; q++) acc[mi][ni][q] = 0.f;

    // stage loader: A 1024 chunks (16B) + B 2048 chunks, 12 per thread
    auto load_stage = [&](int s, int kb) {
        const uint32_t sA = data + s * STAGE_BYTES;
        const uint32_t sB = sA + A_BYTES;
        const char* ga = (const char*)g_embn + (size_t)m0 * (K_DIM * 2) + kb * 128;
        const char* gb = (const char*)g_wn   + (size_t)n0 * (K_DIM * 2) + kb * 128;
#pragma unroll
        for (int i = 0; i < 4; i++) {          // A: 128 rows x 8 chunks
            int v = tid + i * 256;
            uint32_t r = v >> 3, ch = (v & 7) * 16;
            cp16(sA + r * 128 + (ch ^ ((r & 7) << 4)), ga + (size_t)r * (K_DIM * 2) + ch);
        }
#pragma unroll
        for (int i = 0; i < 8; i++) {          // B: 256 rows x 8 chunks
            int v = tid + i * 256;
            uint32_t r = v >> 3, ch = (v & 7) * 16;
            cp16(sB + r * 128 + (ch ^ ((r & 7) << 4)), gb + (size_t)r * (K_DIM * 2) + ch);
        }
        asm volatile("cp.async.commit_group;" ::: "memory");
    };

    // prologue: stages 0..STAGES-2
#pragma unroll
    for (int kb = 0; kb < STAGES - 1; kb++) load_stage(kb, kb);

#pragma unroll 1
    for (int kb = 0; kb < NK; kb++) {
        // keep the group count exact: one commit per iteration, loaded or empty
        if (kb + STAGES - 1 < NK) {
            load_stage((kb + STAGES - 1) % STAGES, kb + STAGES - 1);
        } else {
            asm volatile("cp.async.commit_group;" ::: "memory");
        }
        asm volatile("cp.async.wait_group %0;" :: "n"(STAGES - 2) : "memory");
        __syncthreads();

        const int s = kb % STAGES;
        const uint32_t sA = data + s * STAGE_BYTES;
        const uint32_t sB = sA + A_BYTES;

#pragma unroll
        for (int ks = 0; ks < 4; ks++) {
            const uint32_t kc = ks * 32;       // byte offset of k16 step
            uint32_t a[4][4];
#pragma unroll
            for (int mi = 0; mi < 4; mi++) {
                uint32_t row = warp_m * 64 + mi * 16 + (lane & 15);
                uint32_t col = (kc + ((lane >> 4) << 4)) ^ ((row & 7) << 4);
                LDSM_X4(a[mi][0], a[mi][1], a[mi][2], a[mi][3], sA + row * 128 + col);
            }
            uint32_t b[8][2];
#pragma unroll
            for (int nj = 0; nj < 4; nj++) {
                uint32_t row = warp_n * 64 + nj * 16 + (lane & 7) + ((lane >> 4) << 3);
                uint32_t col = (kc + ((lane & 8) << 1)) ^ ((row & 7) << 4);
                LDSM_X4(b[2 * nj][0], b[2 * nj][1], b[2 * nj + 1][0], b[2 * nj + 1][1],
                        sB + row * 128 + col);
            }
#pragma unroll
            for (int mi = 0; mi < 4; mi++)
#pragma unroll
                for (int ni = 0; ni < 8; ni++)
                    mma16816(acc[mi][ni], a[mi], b[ni]);
        }
        __syncthreads();
    }

    // Epilogue: out = ((1+cos)/2 + 1e-8)/0.05 = 10*cos + (10 + 2e-7)
    const float bias = 10.0f + 2e-7f;
#pragma unroll
    for (int mi = 0; mi < 4; mi++) {
#pragma unroll
        for (int ni = 0; ni < 8; ni++) {
            int r = m0 + warp_m * 64 + mi * 16 + g;
            int c = n0 + warp_n * 64 + ni * 8 + t4 * 2;
            float2 p0 = make_float2(fmaf(acc[mi][ni][0], 10.f, bias),
                                    fmaf(acc[mi][ni][1], 10.f, bias));
            float2 p1 = make_float2(fmaf(acc[mi][ni][2], 10.f, bias),
                                    fmaf(acc[mi][ni][3], 10.f, bias));
            *(float2*)&C[(size_t)r * N_DIM + c]       = p0;
            *(float2*)&C[(size_t)(r + 8) * N_DIM + c] = p1;
        }
    }
}

// ---------------------------------------------------------------------------
extern "C" void kernel_launch(void* const* d_in, const int* in_sizes, int n_in,
                              void* d_out, int out_size) {
    const float* emb    = (const float*)d_in[0];   // [65536, 768] f32
    const float* weight = (const float*)d_in[1];   // [1024, 768]  f32
    float* out = (float*)d_out;                    // [65536, 1024] f32

    normalize_kernel<<<M_DIM / 8, 256>>>(emb, M_DIM, 0);
    normalize_kernel<<<N_DIM / 8, 256>>>(weight, N_DIM, 1);

    cudaFuncSetAttribute(gemm_kernel, cudaFuncAttributeMaxDynamicSharedMemorySize, SMEM_DYN);
    dim3 grid(N_DIM / BN, M_DIM / BM);   // (4, 512)
    gemm_kernel<<<grid, 256, SMEM_DYN>>>(out);
}

// round 11
// speedup vs baseline: 1.0234x; 1.0234x over previous
#include <cuda_runtime.h>
#include <cuda_bf16.h>
#include <cstdint>

// Problem dims (fixed per reference setup_inputs)
#define M_DIM 65536
#define N_DIM 1024
#define K_DIM 768

// GEMM tiling: CTA 128x256, warp 32x64 (4x4 warps, 512 thr), BK=64, 4-stage cp.async
#define BM 128
#define BN 256
#define BK 64
#define NK (K_DIM / BK)            // 12
#define STAGES 4
#define A_BYTES (BM * 128)         // 128 rows x 128B (64 bf16)
#define B_BYTES (BN * 128)         // 256 rows x 128B
#define STAGE_BYTES (A_BYTES + B_BYTES)            // 49152
#define SMEM_DYN (1024 + STAGES * STAGE_BYTES)     // ~197.6 KB

// Scratch: normalized bf16 operands (device globals -- no allocation allowed)
__device__ __nv_bfloat16 g_embn[(size_t)M_DIM * K_DIM];
__device__ __nv_bfloat16 g_wn[(size_t)N_DIM * K_DIM];

// ---------------------------------------------------------------------------
// Row L2-normalize fp32 -> bf16, both tensors in one launch.
// One warp per row (K=768: 6 float4 per lane).
// ---------------------------------------------------------------------------
__global__ void normalize_kernel(const float* __restrict__ emb,
                                 const float* __restrict__ w) {
    int row  = (blockIdx.x * blockDim.x + threadIdx.x) >> 5;
    int lane = threadIdx.x & 31;
    if (row >= M_DIM + N_DIM) return;

    const float* in;
    __nv_bfloat16* out;
    if (row < M_DIM) {
        in  = emb + (size_t)row * K_DIM;
        out = g_embn + (size_t)row * K_DIM;
    } else {
        int r2 = row - M_DIM;
        in  = w + (size_t)r2 * K_DIM;
        out = g_wn + (size_t)r2 * K_DIM;
    }

    const float4* src = (const float4*)in;
    float4 v[6];
    float ss = 0.f;
#pragma unroll
    for (int i = 0; i < 6; i++) {
        v[i] = src[lane + i * 32];
        ss += v[i].x * v[i].x + v[i].y * v[i].y + v[i].z * v[i].z + v[i].w * v[i].w;
    }
#pragma unroll
    for (int o = 16; o > 0; o >>= 1) ss += __shfl_xor_sync(0xffffffffu, ss, o);

    float norm = fmaxf(sqrtf(ss), 1e-8f);   // torch cosine_similarity clamp
    float s = 1.0f / norm;

    __nv_bfloat162* dst = (__nv_bfloat162*)out;
#pragma unroll
    for (int i = 0; i < 6; i++) {
        int idx = lane + i * 32;
        dst[idx * 2 + 0] = __floats2bfloat162_rn(v[i].x * s, v[i].y * s);
        dst[idx * 2 + 1] = __floats2bfloat162_rn(v[i].z * s, v[i].w * s);
    }
}

// ---------------------------------------------------------------------------
// helpers
// ---------------------------------------------------------------------------
__device__ __forceinline__ void cp16(uint32_t saddr, const void* g) {
    asm volatile("cp.async.cg.shared.global [%0], [%1], 16;" :: "r"(saddr), "l"(g));
}

__device__ __forceinline__ void mma16816(float* c, const uint32_t* a, const uint32_t* b) {
    asm volatile(
        "mma.sync.aligned.m16n8k16.row.col.f32.bf16.bf16.f32 "
        "{%0,%1,%2,%3}, {%4,%5,%6,%7}, {%8,%9}, {%0,%1,%2,%3};\n"
        : "+f"(c[0]), "+f"(c[1]), "+f"(c[2]), "+f"(c[3])
        : "r"(a[0]), "r"(a[1]), "r"(a[2]), "r"(a[3]), "r"(b[0]), "r"(b[1]));
}

#define LDSM_X4(r0, r1, r2, r3, addr) \
    asm volatile("ldmatrix.sync.aligned.m8n8.x4.shared.b16 {%0,%1,%2,%3}, [%4];" \
                 : "=r"(r0), "=r"(r1), "=r"(r2), "=r"(r3) : "r"(addr))

// ---------------------------------------------------------------------------
// bf16 mma.sync GEMM: C[M,N] = embn @ wn^T, epilogue 10*cos + (10 + 2e-7)
// smem rows are 128B (64 bf16), SW128-swizzled at 16B granularity:
//   addr(row, bytecol) = row*128 + (bytecol ^ ((row&7)<<4))
// 16 warps: 4 along M (32 rows), 4 along N (64 cols). Fragments double-buffered.
// ---------------------------------------------------------------------------
__global__ __launch_bounds__(512, 1) void gemm_kernel(float* __restrict__ C) {
    extern __shared__ char dsm[];
    const uint32_t raw  = (uint32_t)__cvta_generic_to_shared(dsm);
    const uint32_t data = (raw + 1023) & ~1023u;

    const int tid    = threadIdx.x;
    const int wid    = tid >> 5;
    const int lane   = tid & 31;
    const int warp_m = wid & 3;    // 4 warps along M -> 32 rows each
    const int warp_n = wid >> 2;   // 4 warps along N -> 64 cols each
    const int g  = lane >> 2;      // group 0..7
    const int t4 = lane & 3;

    const int m0 = blockIdx.y * BM;
    const int n0 = blockIdx.x * BN;

    float acc[2][8][4];
#pragma unroll
    for (int mi = 0; mi < 2; mi++)
#pragma unroll
        for (int ni = 0; ni < 8; ni++)
#pragma unroll
            for (int q = 0; q < 4; q++) acc[mi][ni][q] = 0.f;

    // stage loader: A 1024 chunks (16B) + B 2048 chunks, 6 per thread
    auto load_stage = [&](int s, int kb) {
        const uint32_t sA = data + s * STAGE_BYTES;
        const uint32_t sB = sA + A_BYTES;
        const char* ga = (const char*)g_embn + (size_t)m0 * (K_DIM * 2) + kb * 128;
        const char* gb = (const char*)g_wn   + (size_t)n0 * (K_DIM * 2) + kb * 128;
#pragma unroll
        for (int i = 0; i < 2; i++) {          // A: 128 rows x 8 chunks
            int v = tid + i * 512;
            uint32_t r = v >> 3, ch = (v & 7) * 16;
            cp16(sA + r * 128 + (ch ^ ((r & 7) << 4)), ga + (size_t)r * (K_DIM * 2) + ch);
        }
#pragma unroll
        for (int i = 0; i < 4; i++) {          // B: 256 rows x 8 chunks
            int v = tid + i * 512;
            uint32_t r = v >> 3, ch = (v & 7) * 16;
            cp16(sB + r * 128 + (ch ^ ((r & 7) << 4)), gb + (size_t)r * (K_DIM * 2) + ch);
        }
        asm volatile("cp.async.commit_group;" ::: "memory");
    };

    // fragment double buffers
    uint32_t af[2][2][4];   // [buf][mi][4]
    uint32_t bf[2][8][2];   // [buf][ni][2]

    auto ldfrag = [&](int buf, uint32_t sA, uint32_t sB, int ks) {
        const uint32_t kc = ks * 32;           // byte offset of k16 step
#pragma unroll
        for (int mi = 0; mi < 2; mi++) {
            uint32_t row = warp_m * 32 + mi * 16 + (lane & 15);
            uint32_t col = (kc + ((lane >> 4) << 4)) ^ ((row & 7) << 4);
            LDSM_X4(af[buf][mi][0], af[buf][mi][1], af[buf][mi][2], af[buf][mi][3],
                    sA + row * 128 + col);
        }
#pragma unroll
        for (int nj = 0; nj < 4; nj++) {
            uint32_t row = warp_n * 64 + nj * 16 + (lane & 7) + ((lane >> 4) << 3);
            uint32_t col = (kc + ((lane & 8) << 1)) ^ ((row & 7) << 4);
            LDSM_X4(bf[buf][2 * nj][0], bf[buf][2 * nj][1],
                    bf[buf][2 * nj + 1][0], bf[buf][2 * nj + 1][1],
                    sB + row * 128 + col);
        }
    };

    // prologue: stages 0..STAGES-2
#pragma unroll
    for (int kb = 0; kb < STAGES - 1; kb++) load_stage(kb, kb);

#pragma unroll 1
    for (int kb = 0; kb < NK; kb++) {
        // keep the group count exact: one commit per iteration, loaded or empty
        if (kb + STAGES - 1 < NK) {
            load_stage((kb + STAGES - 1) % STAGES, kb + STAGES - 1);
        } else {
            asm volatile("cp.async.commit_group;" ::: "memory");
        }
        asm volatile("cp.async.wait_group %0;" :: "n"(STAGES - 2) : "memory");
        __syncthreads();

        const int s = kb % STAGES;
        const uint32_t sA = data + s * STAGE_BYTES;
        const uint32_t sB = sA + A_BYTES;

        ldfrag(0, sA, sB, 0);
#pragma unroll
        for (int ks = 0; ks < 4; ks++) {
            if (ks < 3) ldfrag((ks + 1) & 1, sA, sB, ks + 1);
            const int cur = ks & 1;
#pragma unroll
            for (int mi = 0; mi < 2; mi++)
#pragma unroll
                for (int ni = 0; ni < 8; ni++)
                    mma16816(acc[mi][ni], af[cur][mi], bf[cur][ni]);
        }
        __syncthreads();
    }

    // Epilogue: out = ((1+cos)/2 + 1e-8)/0.05 = 10*cos + (10 + 2e-7)
    const float bias = 10.0f + 2e-7f;
#pragma unroll
    for (int mi = 0; mi < 2; mi++) {
#pragma unroll
        for (int ni = 0; ni < 8; ni++) {
            int r = m0 + warp_m * 32 + mi * 16 + g;
            int c = n0 + warp_n * 64 + ni * 8 + t4 * 2;
            float2 p0 = make_float2(fmaf(acc[mi][ni][0], 10.f, bias),
                                    fmaf(acc[mi][ni][1], 10.f, bias));
            float2 p1 = make_float2(fmaf(acc[mi][ni][2], 10.f, bias),
                                    fmaf(acc[mi][ni][3], 10.f, bias));
            *(float2*)&C[(size_t)r * N_DIM + c]       = p0;
            *(float2*)&C[(size_t)(r + 8) * N_DIM + c] = p1;
        }
    }
}

// ---------------------------------------------------------------------------
extern "C" void kernel_launch(void* const* d_in, const int* in_sizes, int n_in,
                              void* d_out, int out_size) {
    const float* emb    = (const float*)d_in[0];   // [65536, 768] f32
    const float* weight = (const float*)d_in[1];   // [1024, 768]  f32
    float* out = (float*)d_out;                    // [65536, 1024] f32

    // 8 rows per block, emb + weight in one launch
    normalize_kernel<<<(M_DIM + N_DIM) / 8, 256>>>(emb, weight);

    cudaFuncSetAttribute(gemm_kernel, cudaFuncAttributeMaxDynamicSharedMemorySize, SMEM_DYN);
    dim3 grid(N_DIM / BN, M_DIM / BM);   // (4, 512)
    gemm_kernel<<<grid, 512, SMEM_DYN>>>(out);
}

// round 16
// speedup vs baseline: 1.1615x; 1.1350x over previous
#include <cuda_runtime.h>
#include <cuda_bf16.h>
#include <cstdint>

// Problem dims (fixed per reference setup_inputs)
#define M_DIM 65536
#define N_DIM 1024
#define K_DIM 768

// GEMM tiling: CTA 128x128, 8 warps (2 M x 4 N -> warp 64x32), BK=64,
// 3-stage cp.async, 2 CTAs/SM co-resident.
#define BM 128
#define BN 128
#define BK 64
#define NK (K_DIM / BK)            // 12
#define STAGES 3
#define A_BYTES (BM * 128)         // 128 rows x 128B (64 bf16)
#define B_BYTES (BN * 128)
#define STAGE_BYTES (A_BYTES + B_BYTES)            // 32768
#define SMEM_DYN (1024 + STAGES * STAGE_BYTES)     // ~97.3 KB -> 2 CTAs/SM

// Scratch: normalized bf16 operands (device globals -- no allocation allowed)
__device__ __nv_bfloat16 g_embn[(size_t)M_DIM * K_DIM];
__device__ __nv_bfloat16 g_wn[(size_t)N_DIM * K_DIM];

// ---------------------------------------------------------------------------
// Row L2-normalize fp32 -> bf16, both tensors in one launch.
// One warp per row (K=768: 6 float4 per lane).
// ---------------------------------------------------------------------------
__global__ void normalize_kernel(const float* __restrict__ emb,
                                 const float* __restrict__ w) {
    int row  = (blockIdx.x * blockDim.x + threadIdx.x) >> 5;
    int lane = threadIdx.x & 31;
    if (row >= M_DIM + N_DIM) return;

    const float* in;
    __nv_bfloat16* out;
    if (row < M_DIM) {
        in  = emb + (size_t)row * K_DIM;
        out = g_embn + (size_t)row * K_DIM;
    } else {
        int r2 = row - M_DIM;
        in  = w + (size_t)r2 * K_DIM;
        out = g_wn + (size_t)r2 * K_DIM;
    }

    const float4* src = (const float4*)in;
    float4 v[6];
    float ss = 0.f;
#pragma unroll
    for (int i = 0; i < 6; i++) {
        v[i] = src[lane + i * 32];
        ss += v[i].x * v[i].x + v[i].y * v[i].y + v[i].z * v[i].z + v[i].w * v[i].w;
    }
#pragma unroll
    for (int o = 16; o > 0; o >>= 1) ss += __shfl_xor_sync(0xffffffffu, ss, o);

    float norm = fmaxf(sqrtf(ss), 1e-8f);   // torch cosine_similarity clamp
    float s = 1.0f / norm;

    __nv_bfloat162* dst = (__nv_bfloat162*)out;
#pragma unroll
    for (int i = 0; i < 6; i++) {
        int idx = lane + i * 32;
        dst[idx * 2 + 0] = __floats2bfloat162_rn(v[i].x * s, v[i].y * s);
        dst[idx * 2 + 1] = __floats2bfloat162_rn(v[i].z * s, v[i].w * s);
    }
}

// ---------------------------------------------------------------------------
// helpers
// ---------------------------------------------------------------------------
__device__ __forceinline__ void cp16(uint32_t saddr, const void* g) {
    asm volatile("cp.async.cg.shared.global [%0], [%1], 16;" :: "r"(saddr), "l"(g));
}

__device__ __forceinline__ void mma16816(float* c, const uint32_t* a, const uint32_t* b) {
    asm volatile(
        "mma.sync.aligned.m16n8k16.row.col.f32.bf16.bf16.f32 "
        "{%0,%1,%2,%3}, {%4,%5,%6,%7}, {%8,%9}, {%0,%1,%2,%3};\n"
        : "+f"(c[0]), "+f"(c[1]), "+f"(c[2]), "+f"(c[3])
        : "r"(a[0]), "r"(a[1]), "r"(a[2]), "r"(a[3]), "r"(b[0]), "r"(b[1]));
}

#define LDSM_X4(r0, r1, r2, r3, addr) \
    asm volatile("ldmatrix.sync.aligned.m8n8.x4.shared.b16 {%0,%1,%2,%3}, [%4];" \
                 : "=r"(r0), "=r"(r1), "=r"(r2), "=r"(r3) : "r"(addr))

// ---------------------------------------------------------------------------
// bf16 mma.sync GEMM: C[M,N] = embn @ wn^T, epilogue 10*cos + (10 + 2e-7)
// smem rows are 128B (64 bf16), SW128-swizzled at 16B granularity:
//   addr(row, bytecol) = row*128 + (bytecol ^ ((row&7)<<4))
// 8 warps: 2 along M (64 rows), 4 along N (32 cols). 2 CTAs/SM.
// ---------------------------------------------------------------------------
__global__ __launch_bounds__(256, 2) void gemm_kernel(float* __restrict__ C) {
    extern __shared__ char dsm[];
    const uint32_t raw  = (uint32_t)__cvta_generic_to_shared(dsm);
    const uint32_t data = (raw + 1023) & ~1023u;

    const int tid    = threadIdx.x;
    const int wid    = tid >> 5;
    const int lane   = tid & 31;
    const int warp_m = wid & 1;    // 2 warps along M -> 64 rows each
    const int warp_n = wid >> 1;   // 4 warps along N -> 32 cols each
    const int g  = lane >> 2;      // group 0..7
    const int t4 = lane & 3;

    const int m0 = blockIdx.y * BM;
    const int n0 = blockIdx.x * BN;

    float acc[4][4][4];
#pragma unroll
    for (int mi = 0; mi < 4; mi++)
#pragma unroll
        for (int ni = 0; ni < 4; ni++)
#pragma unroll
            for (int q = 0; q < 4; q++) acc[mi][ni][q] = 0.f;

    // stage loader: A 1024 + B 1024 chunks (16B), 8 per thread
    auto load_stage = [&](int s, int kb) {
        const uint32_t sA = data + s * STAGE_BYTES;
        const uint32_t sB = sA + A_BYTES;
        const char* ga = (const char*)g_embn + (size_t)m0 * (K_DIM * 2) + kb * 128;
        const char* gb = (const char*)g_wn   + (size_t)n0 * (K_DIM * 2) + kb * 128;
#pragma unroll
        for (int i = 0; i < 4; i++) {          // A: 128 rows x 8 chunks
            int v = tid + i * 256;
            uint32_t r = v >> 3, ch = (v & 7) * 16;
            cp16(sA + r * 128 + (ch ^ ((r & 7) << 4)), ga + (size_t)r * (K_DIM * 2) + ch);
        }
#pragma unroll
        for (int i = 0; i < 4; i++) {          // B: 128 rows x 8 chunks
            int v = tid + i * 256;
            uint32_t r = v >> 3, ch = (v & 7) * 16;
            cp16(sB + r * 128 + (ch ^ ((r & 7) << 4)), gb + (size_t)r * (K_DIM * 2) + ch);
        }
        asm volatile("cp.async.commit_group;" ::: "memory");
    };

    // prologue: stages 0..STAGES-2
#pragma unroll
    for (int kb = 0; kb < STAGES - 1; kb++) load_stage(kb, kb);

#pragma unroll 1
    for (int kb = 0; kb < NK; kb++) {
        // keep the group count exact: one commit per iteration, loaded or empty
        if (kb + STAGES - 1 < NK) {
            load_stage((kb + STAGES - 1) % STAGES, kb + STAGES - 1);
        } else {
            asm volatile("cp.async.commit_group;" ::: "memory");
        }
        asm volatile("cp.async.wait_group %0;" :: "n"(STAGES - 2) : "memory");
        __syncthreads();

        const int s = kb % STAGES;
        const uint32_t sA = data + s * STAGE_BYTES;
        const uint32_t sB = sA + A_BYTES;

#pragma unroll
        for (int ks = 0; ks < 4; ks++) {
            const uint32_t kc = ks * 32;       // byte offset of k16 step
            uint32_t a[4][4];
#pragma unroll
            for (int mi = 0; mi < 4; mi++) {
                uint32_t row = warp_m * 64 + mi * 16 + (lane & 15);
                uint32_t col = (kc + ((lane >> 4) << 4)) ^ ((row & 7) << 4);
                LDSM_X4(a[mi][0], a[mi][1], a[mi][2], a[mi][3], sA + row * 128 + col);
            }
            uint32_t b[4][2];
#pragma unroll
            for (int nj = 0; nj < 2; nj++) {
                uint32_t row = warp_n * 32 + nj * 16 + (lane & 7) + ((lane >> 4) << 3);
                uint32_t col = (kc + ((lane & 8) << 1)) ^ ((row & 7) << 4);
                LDSM_X4(b[2 * nj][0], b[2 * nj][1], b[2 * nj + 1][0], b[2 * nj + 1][1],
                        sB + row * 128 + col);
            }
#pragma unroll
            for (int mi = 0; mi < 4; mi++)
#pragma unroll
                for (int ni = 0; ni < 4; ni++)
                    mma16816(acc[mi][ni], a[mi], b[ni]);
        }
        __syncthreads();
    }

    // Epilogue: out = ((1+cos)/2 + 1e-8)/0.05 = 10*cos + (10 + 2e-7)
    const float bias = 10.0f + 2e-7f;
#pragma unroll
    for (int mi = 0; mi < 4; mi++) {
#pragma unroll
        for (int ni = 0; ni < 4; ni++) {
            int r = m0 + warp_m * 64 + mi * 16 + g;
            int c = n0 + warp_n * 32 + ni * 8 + t4 * 2;
            float2 p0 = make_float2(fmaf(acc[mi][ni][0], 10.f, bias),
                                    fmaf(acc[mi][ni][1], 10.f, bias));
            float2 p1 = make_float2(fmaf(acc[mi][ni][2], 10.f, bias),
                                    fmaf(acc[mi][ni][3], 10.f, bias));
            *(float2*)&C[(size_t)r * N_DIM + c]       = p0;
            *(float2*)&C[(size_t)(r + 8) * N_DIM + c] = p1;
        }
    }
}

// ---------------------------------------------------------------------------
extern "C" void kernel_launch(void* const* d_in, const int* in_sizes, int n_in,
                              void* d_out, int out_size) {
    const float* emb    = (const float*)d_in[0];   // [65536, 768] f32
    const float* weight = (const float*)d_in[1];   // [1024, 768]  f32
    float* out = (float*)d_out;                    // [65536, 1024] f32

    // 8 rows per block, emb + weight in one launch
    normalize_kernel<<<(M_DIM + N_DIM) / 8, 256>>>(emb, weight);

    cudaFuncSetAttribute(gemm_kernel, cudaFuncAttributeMaxDynamicSharedMemorySize, SMEM_DYN);
    dim3 grid(N_DIM / BN, M_DIM / BM);   // (8, 512): x fastest -> A band L2 reuse
    gemm_kernel<<<grid, 256, SMEM_DYN>>>(out);
}

// round 17
// speedup vs baseline: 1.1678x; 1.0054x over previous
#include <cuda_runtime.h>
#include <cuda_bf16.h>
#include <cstdint>

// Problem dims (fixed per reference setup_inputs)
#define M_DIM 65536
#define N_DIM 1024
#define K_DIM 768

// GEMM tiling: CTA 128x128, 8 warps (2 M x 4 N -> warp 64x32), BK=64,
// 3-stage cp.async, 2 CTAs/SM co-resident, single sync/iter, frag double-buffer.
#define BM 128
#define BN 128
#define BK 64
#define NK (K_DIM / BK)            // 12
#define STAGES 3
#define A_BYTES (BM * 128)         // 128 rows x 128B (64 bf16)
#define B_BYTES (BN * 128)
#define STAGE_BYTES (A_BYTES + B_BYTES)            // 32768
#define SMEM_DYN (1024 + STAGES * STAGE_BYTES)     // ~97.3 KB -> 2 CTAs/SM

// Scratch: normalized bf16 operands (device globals -- no allocation allowed)
__device__ __nv_bfloat16 g_embn[(size_t)M_DIM * K_DIM];
__device__ __nv_bfloat16 g_wn[(size_t)N_DIM * K_DIM];

// ---------------------------------------------------------------------------
// Row L2-normalize fp32 -> bf16, both tensors in one launch.
// One warp per row (K=768: 6 float4 per lane).
// ---------------------------------------------------------------------------
__global__ void normalize_kernel(const float* __restrict__ emb,
                                 const float* __restrict__ w) {
    int row  = (blockIdx.x * blockDim.x + threadIdx.x) >> 5;
    int lane = threadIdx.x & 31;
    if (row >= M_DIM + N_DIM) return;

    const float* in;
    __nv_bfloat16* out;
    if (row < M_DIM) {
        in  = emb + (size_t)row * K_DIM;
        out = g_embn + (size_t)row * K_DIM;
    } else {
        int r2 = row - M_DIM;
        in  = w + (size_t)r2 * K_DIM;
        out = g_wn + (size_t)r2 * K_DIM;
    }

    const float4* src = (const float4*)in;
    float4 v[6];
    float ss = 0.f;
#pragma unroll
    for (int i = 0; i < 6; i++) {
        v[i] = src[lane + i * 32];
        ss += v[i].x * v[i].x + v[i].y * v[i].y + v[i].z * v[i].z + v[i].w * v[i].w;
    }
#pragma unroll
    for (int o = 16; o > 0; o >>= 1) ss += __shfl_xor_sync(0xffffffffu, ss, o);

    float norm = fmaxf(sqrtf(ss), 1e-8f);   // torch cosine_similarity clamp
    float s = 1.0f / norm;

    __nv_bfloat162* dst = (__nv_bfloat162*)out;
#pragma unroll
    for (int i = 0; i < 6; i++) {
        int idx = lane + i * 32;
        dst[idx * 2 + 0] = __floats2bfloat162_rn(v[i].x * s, v[i].y * s);
        dst[idx * 2 + 1] = __floats2bfloat162_rn(v[i].z * s, v[i].w * s);
    }
}

// ---------------------------------------------------------------------------
// helpers
// ---------------------------------------------------------------------------
__device__ __forceinline__ void cp16(uint32_t saddr, const void* g) {
    asm volatile("cp.async.cg.shared.global [%0], [%1], 16;" :: "r"(saddr), "l"(g));
}

__device__ __forceinline__ void mma16816(float* c, const uint32_t* a, const uint32_t* b) {
    asm volatile(
        "mma.sync.aligned.m16n8k16.row.col.f32.bf16.bf16.f32 "
        "{%0,%1,%2,%3}, {%4,%5,%6,%7}, {%8,%9}, {%0,%1,%2,%3};\n"
        : "+f"(c[0]), "+f"(c[1]), "+f"(c[2]), "+f"(c[3])
        : "r"(a[0]), "r"(a[1]), "r"(a[2]), "r"(a[3]), "r"(b[0]), "r"(b[1]));
}

#define LDSM_X4(r0, r1, r2, r3, addr) \
    asm volatile("ldmatrix.sync.aligned.m8n8.x4.shared.b16 {%0,%1,%2,%3}, [%4];" \
                 : "=r"(r0), "=r"(r1), "=r"(r2), "=r"(r3) : "r"(addr))

// ---------------------------------------------------------------------------
// bf16 mma.sync GEMM: C[M,N] = embn @ wn^T, epilogue 10*cos + (10 + 2e-7)
// smem rows are 128B (64 bf16), SW128-swizzled at 16B granularity:
//   addr(row, bytecol) = row*128 + (bytecol ^ ((row&7)<<4))
// 8 warps: 2 along M (64 rows), 4 along N (32 cols). 2 CTAs/SM.
// Loop order per kb: wait -> ONE sync -> issue next loads -> pipelined frags+MMA.
// ---------------------------------------------------------------------------
__global__ __launch_bounds__(256, 2) void gemm_kernel(float* __restrict__ C) {
    extern __shared__ char dsm[];
    const uint32_t raw  = (uint32_t)__cvta_generic_to_shared(dsm);
    const uint32_t data = (raw + 1023) & ~1023u;

    const int tid    = threadIdx.x;
    const int wid    = tid >> 5;
    const int lane   = tid & 31;
    const int warp_m = wid & 1;    // 2 warps along M -> 64 rows each
    const int warp_n = wid >> 1;   // 4 warps along N -> 32 cols each
    const int g  = lane >> 2;      // group 0..7
    const int t4 = lane & 3;

    const int m0 = blockIdx.y * BM;
    const int n0 = blockIdx.x * BN;

    float acc[4][4][4];
#pragma unroll
    for (int mi = 0; mi < 4; mi++)
#pragma unroll
        for (int ni = 0; ni < 4; ni++)
#pragma unroll
            for (int q = 0; q < 4; q++) acc[mi][ni][q] = 0.f;

    // stage loader: A 1024 + B 1024 chunks (16B), 8 per thread
    auto load_stage = [&](int s, int kb) {
        const uint32_t sA = data + s * STAGE_BYTES;
        const uint32_t sB = sA + A_BYTES;
        const char* ga = (const char*)g_embn + (size_t)m0 * (K_DIM * 2) + kb * 128;
        const char* gb = (const char*)g_wn   + (size_t)n0 * (K_DIM * 2) + kb * 128;
#pragma unroll
        for (int i = 0; i < 4; i++) {          // A: 128 rows x 8 chunks
            int v = tid + i * 256;
            uint32_t r = v >> 3, ch = (v & 7) * 16;
            cp16(sA + r * 128 + (ch ^ ((r & 7) << 4)), ga + (size_t)r * (K_DIM * 2) + ch);
        }
#pragma unroll
        for (int i = 0; i < 4; i++) {          // B: 128 rows x 8 chunks
            int v = tid + i * 256;
            uint32_t r = v >> 3, ch = (v & 7) * 16;
            cp16(sB + r * 128 + (ch ^ ((r & 7) << 4)), gb + (size_t)r * (K_DIM * 2) + ch);
        }
        asm volatile("cp.async.commit_group;" ::: "memory");
    };

    // fragment double buffers: 32 + 16 regs
    uint32_t af[2][4][4];
    uint32_t bf[2][4][2];

    auto ldfrag = [&](int buf, uint32_t sA, uint32_t sB, int ks) {
        const uint32_t kc = ks * 32;           // byte offset of k16 step
#pragma unroll
        for (int mi = 0; mi < 4; mi++) {
            uint32_t row = warp_m * 64 + mi * 16 + (lane & 15);
            uint32_t col = (kc + ((lane >> 4) << 4)) ^ ((row & 7) << 4);
            LDSM_X4(af[buf][mi][0], af[buf][mi][1], af[buf][mi][2], af[buf][mi][3],
                    sA + row * 128 + col);
        }
#pragma unroll
        for (int nj = 0; nj < 2; nj++) {
            uint32_t row = warp_n * 32 + nj * 16 + (lane & 7) + ((lane >> 4) << 3);
            uint32_t col = (kc + ((lane & 8) << 1)) ^ ((row & 7) << 4);
            LDSM_X4(bf[buf][2 * nj][0], bf[buf][2 * nj][1],
                    bf[buf][2 * nj + 1][0], bf[buf][2 * nj + 1][1],
                    sB + row * 128 + col);
        }
    };

    // prologue: stages 0..STAGES-2
#pragma unroll
    for (int kb = 0; kb < STAGES - 1; kb++) load_stage(kb, kb);

#pragma unroll 1
    for (int kb = 0; kb < NK; kb++) {
        // stage kb is complete once only the most recent group can be pending
        asm volatile("cp.async.wait_group 1;" ::: "memory");
        __syncthreads();   // also: everyone done reading the stage we overwrite next

        // issue next stage load AFTER the sync (overwrites stage read last iter);
        // commit every iteration so wait_group's positional count stays exact
        if (kb + STAGES - 1 < NK) {
            load_stage((kb + STAGES - 1) % STAGES, kb + STAGES - 1);
        } else {
            asm volatile("cp.async.commit_group;" ::: "memory");
        }

        const int s = kb % STAGES;
        const uint32_t sA = data + s * STAGE_BYTES;
        const uint32_t sB = sA + A_BYTES;

        ldfrag(0, sA, sB, 0);
#pragma unroll
        for (int ks = 0; ks < 4; ks++) {
            if (ks < 3) ldfrag((ks + 1) & 1, sA, sB, ks + 1);   // prefetch next k-step
            const int cur = ks & 1;
#pragma unroll
            for (int mi = 0; mi < 4; mi++)
#pragma unroll
                for (int ni = 0; ni < 4; ni++)
                    mma16816(acc[mi][ni], af[cur][mi], bf[cur][ni]);
        }
    }

    // Epilogue: out = ((1+cos)/2 + 1e-8)/0.05 = 10*cos + (10 + 2e-7)
    const float bias = 10.0f + 2e-7f;
#pragma unroll
    for (int mi = 0; mi < 4; mi++) {
#pragma unroll
        for (int ni = 0; ni < 4; ni++) {
            int r = m0 + warp_m * 64 + mi * 16 + g;
            int c = n0 + warp_n * 32 + ni * 8 + t4 * 2;
            float2 p0 = make_float2(fmaf(acc[mi][ni][0], 10.f, bias),
                                    fmaf(acc[mi][ni][1], 10.f, bias));
            float2 p1 = make_float2(fmaf(acc[mi][ni][2], 10.f, bias),
                                    fmaf(acc[mi][ni][3], 10.f, bias));
            *(float2*)&C[(size_t)r * N_DIM + c]       = p0;
            *(float2*)&C[(size_t)(r + 8) * N_DIM + c] = p1;
        }
    }
}

// ---------------------------------------------------------------------------
extern "C" void kernel_launch(void* const* d_in, const int* in_sizes, int n_in,
                              void* d_out, int out_size) {
    const float* emb    = (const float*)d_in[0];   // [65536, 768] f32
    const float* weight = (const float*)d_in[1];   // [1024, 768]  f32
    float* out = (float*)d_out;                    // [65536, 1024] f32

    // 8 rows per block, emb + weight in one launch
    normalize_kernel<<<(M_DIM + N_DIM) / 8, 256>>>(emb, weight);

    cudaFuncSetAttribute(gemm_kernel, cudaFuncAttributeMaxDynamicSharedMemorySize, SMEM_DYN);
    dim3 grid(N_DIM / BN, M_DIM / BM);   // (8, 512): x fastest -> A band L2 reuse
    gemm_kernel<<<grid, 256, SMEM_DYN>>>(out);
}